// round 4
// baseline (speedup 1.0000x reference)
#include <cuda_runtime.h>

#define BB   32
#define CC   3072
#define HWD  784
#define KK   11
#define NCLS 200
#define NPX  392            // HWD/2, u64 pixel slots per channel row
#define NB1  14             // pixel blocks in k1 (14*28 u64 = 392)
#define CB2  128            // channels per CTA in k2

typedef unsigned long long u64;

// ---- scratch (static device memory; no allocations) ----
__device__ float g_asq[KK];
__device__ float g_fsT[CC * BB];            // sum_k afm, transposed [c][b]
__device__ float g_attnp[NB1 * BB * KK];    // attn partials per pixel-block

// ---- packed f32x2 helpers (sm_10x) ----
__device__ __forceinline__ u64 fma2(u64 a, u64 b, u64 c) {
    u64 d; asm("fma.rn.f32x2 %0, %1, %2, %3;" : "=l"(d) : "l"(a), "l"(b), "l"(c)); return d;
}
__device__ __forceinline__ u64 add2(u64 a, u64 b) {
    u64 d; asm("add.rn.f32x2 %0, %1, %2;" : "=l"(d) : "l"(a), "l"(b)); return d;
}
__device__ __forceinline__ u64 pk(float lo, float hi) {
    u64 d; asm("mov.b64 %0, {%1, %2};" : "=l"(d) : "f"(lo), "f"(hi)); return d;
}
__device__ __forceinline__ void upk(u64 v, float& lo, float& hi) {
    asm("mov.b64 {%0, %1}, %2;" : "=f"(lo), "=f"(hi) : "l"(v));
}

// ================= kernel 0: a_sq[k] = sum_c w_land[k,c]^2 =================
__global__ void k_asq(const float* __restrict__ w_land) {
    int w = threadIdx.x >> 5, lane = threadIdx.x & 31;   // 11 warps
    float s = 0.f;
    for (int c = lane; c < CC; c += 32) { float v = w_land[w * CC + c]; s += v * v; }
    #pragma unroll
    for (int o = 16; o; o >>= 1) s += __shfl_down_sync(0xffffffffu, s, o);
    if (lane == 0) g_asq[w] = s;
}

// ======= kernel 1: fused ab (full-C) + softmax + maps + attn partials ======
// grid (NB1=14, B), block 256 (8 warps; lanes 0-27 compute). Each lane owns
// one u64 pixel slot; warps split the 3072 channels 8-way; weights staged in
// 128-channel chunks as pre-duplicated (w,w) u64. Epilogue: smem reduce over
// 8 warps, then softmax over k per pixel, maps + attn partial out.
__global__ void __launch_bounds__(256) k1(const float* __restrict__ x,
                                          const float* __restrict__ w_land,
                                          float* __restrict__ out_maps) {
    const int b = blockIdx.y, bx = blockIdx.x;
    const int tid = threadIdx.x, warp = tid >> 5, lane = tid & 31;
    __shared__ u64 wsm[128 * KK];            // 11.3 KB
    __shared__ u64 psum[8 * KK * 28];        // 19.7 KB
    __shared__ float redf[KK * 56];          // 2.46 KB
    __shared__ float smp[KK * 56];           // 2.46 KB

    const int ln = (lane < 28) ? lane : 27;  // clamp inactive lanes
    const int s = bx * 28 + ln;              // u64 pixel slot 0..391
    const u64* xg = (const u64*)x + (size_t)b * CC * NPX;

    u64 acc[KK];
    #pragma unroll
    for (int k = 0; k < KK; k++) acc[k] = 0ull;

    for (int chunk = 0; chunk < 24; chunk++) {
        const int cch = chunk * 128;
        for (int i = tid; i < 128 * KK; i += 256) {
            int c = i / KK, k = i - c * KK;
            float wv = w_land[k * CC + cch + c];
            wsm[i] = pk(wv, wv);
        }
        __syncthreads();
        const int cbase = cch + warp * 16;
        u64 xv = xg[(size_t)cbase * NPX + s];
        #pragma unroll
        for (int c16 = 0; c16 < 16; c16++) {
            u64 xn = (c16 + 1 < 16) ? xg[(size_t)(cbase + c16 + 1) * NPX + s] : xv;
            const u64* wr = &wsm[(warp * 16 + c16) * KK];
            #pragma unroll
            for (int k = 0; k < KK; k++) acc[k] = fma2(xv, wr[k], acc[k]);
            xv = xn;
        }
        __syncthreads();
    }

    // cross-warp reduce
    if (lane < 28) {
        #pragma unroll
        for (int k = 0; k < KK; k++) psum[(warp * KK + k) * 28 + lane] = acc[k];
    }
    __syncthreads();
    for (int i = tid; i < KK * 28; i += 256) {   // FIX: 308 slots, 256 threads
        int k = i / 28, sl = i - k * 28;
        u64 v = 0ull;
        #pragma unroll
        for (int w = 0; w < 8; w++) v = add2(v, psum[(w * KK + k) * 28 + sl]);
        float lo, hi; upk(v, lo, hi);
        redf[k * 56 + 2 * sl]     = lo;
        redf[k * 56 + 2 * sl + 1] = hi;
    }
    __syncthreads();
    // softmax over k per pixel (b_sq cancels: logits = 2*ab - a_sq)
    if (tid < 56) {
        float v[KK];
        float m = -1e30f;
        #pragma unroll
        for (int k = 0; k < KK; k++) {
            v[k] = 2.f * redf[k * 56 + tid] - g_asq[k];
            m = fmaxf(m, v[k]);
        }
        float tot = 0.f;
        #pragma unroll
        for (int k = 0; k < KK; k++) { v[k] = __expf(v[k] - m); tot += v[k]; }
        float inv = 1.f / tot;
        #pragma unroll
        for (int k = 0; k < KK; k++) {
            float mp = v[k] * inv;
            out_maps[((size_t)b * KK + k) * HWD + bx * 56 + tid] = mp;
            smp[k * 56 + tid] = mp;
        }
    }
    __syncthreads();
    if (tid < KK) {
        float t = 0.f;
        #pragma unroll 8
        for (int p = 0; p < 56; p++) t += smp[tid * 56 + p];
        g_attnp[(bx * BB + b) * KK + tid] = t;
    }
}

// ===== kernel 2: afm[b,c,k] = (sum_p maps[k,p] x[c,p])/784 * mod[c,k] ======
// grid (24, B), block 128. x staged into smem COALESCED in 56-pixel chunks
// (u64 rows padded to 33 -> conflict-free channel-per-lane LDS.64). Maps read
// as broadcast u64 pixel-pairs. Also writes g_fsT and finishes attn.
__global__ void __launch_bounds__(128) k2(const float* __restrict__ x,
                                          const float* __restrict__ maps,
                                          const float* __restrict__ modulation,
                                          float* __restrict__ out_afm,
                                          float* __restrict__ out_attn) {
    const int b = blockIdx.y, bx = blockIdx.x;
    const int tid = threadIdx.x;
    const int c0 = bx * CB2;
    __shared__ u64 xs[CB2 * 33];             // 33.8 KB (pad 28->33: conflict-free)
    __shared__ u64 mm[KK * 28];              // 2.46 KB

    if (bx == 0 && tid < KK) {               // finish attn (g_attnp ready)
        float t = 0.f;
        #pragma unroll
        for (int q = 0; q < NB1; q++) t += g_attnp[(q * BB + b) * KK + tid];
        out_attn[b * KK + tid] = t;
    }

    const u64* xg = (const u64*)x + ((size_t)b * CC + c0) * NPX;
    const u64* mg = (const u64*)maps + (size_t)b * KK * NPX;

    u64 acc[KK];
    #pragma unroll
    for (int k = 0; k < KK; k++) acc[k] = 0ull;

    for (int pc = 0; pc < NB1; pc++) {
        const int p0 = pc * 28;
        #pragma unroll
        for (int i = 0; i < 28; i++) {       // 28 u64 per thread, coalesced
            int idx = i * 128 + tid;
            int ch = idx / 28, j = idx - ch * 28;
            xs[ch * 33 + j] = xg[(size_t)ch * NPX + p0 + j];
        }
        for (int i = tid; i < KK * 28; i += 128) {
            int k = i / 28, j = i - k * 28;
            mm[i] = mg[(size_t)k * NPX + p0 + j];
        }
        __syncthreads();
        #pragma unroll 4
        for (int j = 0; j < 28; j++) {
            u64 xa = xs[tid * 33 + j];
            #pragma unroll
            for (int k = 0; k < KK; k++) acc[k] = fma2(xa, mm[k * 28 + j], acc[k]);
        }
        __syncthreads();
    }

    const float inv = 1.f / 784.f;
    const int c = c0 + tid;
    float fs = 0.f;
    #pragma unroll
    for (int k = 0; k < KK; k++) {
        float lo, hi; upk(acc[k], lo, hi);
        float v = (lo + hi) * inv * modulation[c * KK + k];
        out_afm[((size_t)b * CC + c) * KK + k] = v;
        fs += v;
    }
    g_fsT[c * BB + b] = fs;
}

// ===== kernel 3: scores[b,n] = sum_c fsT[c][b] * w_cls[n,c] ================
__global__ void __launch_bounds__(256) k_scores(const float* __restrict__ w_cls,
                                                float* __restrict__ out_scores) {
    const int n0 = blockIdx.x * 4;
    const int g = threadIdx.x >> 6;                       // 0..3
    const int l = threadIdx.x & 63;
    const int n = n0 + g;
    u64 acc[16];
    #pragma unroll
    for (int j = 0; j < 16; j++) acc[j] = 0ull;
    for (int c = l; c < CC; c += 64) {
        float wv = w_cls[(size_t)n * CC + c];
        u64 wp = pk(wv, wv);
        const u64* fr = (const u64*)(g_fsT + c * BB);
        #pragma unroll
        for (int j = 0; j < 16; j++) acc[j] = fma2(fr[j], wp, acc[j]);
    }
    __shared__ u64 gt[8][16];
    int lane = threadIdx.x & 31, wid = threadIdx.x >> 5;
    #pragma unroll
    for (int j = 0; j < 16; j++) {
        u64 v = acc[j];
        #pragma unroll
        for (int o = 16; o; o >>= 1) v = add2(v, __shfl_down_sync(0xffffffffu, v, o));
        if (lane == 0) gt[wid][j] = v;
    }
    __syncthreads();
    if (threadIdx.x < 64) {
        int gg = threadIdx.x >> 4, j = threadIdx.x & 15;
        u64 v = add2(gt[2 * gg][j], gt[2 * gg + 1][j]);
        float f0, f1; upk(v, f0, f1);
        out_scores[(2 * j) * NCLS + n0 + gg]     = f0;    // b = 2j
        out_scores[(2 * j + 1) * NCLS + n0 + gg] = f1;    // b = 2j+1
    }
}

// ============================== launch =====================================
extern "C" void kernel_launch(void* const* d_in, const int* in_sizes, int n_in,
                              void* d_out, int out_size) {
    const float* x          = (const float*)d_in[0];
    const float* w_land     = (const float*)d_in[1];
    const float* modulation = (const float*)d_in[2];
    const float* w_cls      = (const float*)d_in[3];
    float* out        = (float*)d_out;
    float* out_afm    = out;                               // (B,C,K)  1081344
    float* out_scores = out + 1081344;                     // (B,NC)      6400
    float* out_maps   = out + 1087744;                     // (B,K,H,W) 275968
    float* out_attn   = out + 1363712;                     // (B,K)        352

    k_asq<<<1, 352>>>(w_land);
    k1<<<dim3(NB1, BB), 256>>>(x, w_land, out_maps);
    k2<<<dim3(CC / CB2, BB), 128>>>(x, out_maps, modulation, out_afm, out_attn);
    k_scores<<<50, 256>>>(w_cls, out_scores);
}